// round 15
// baseline (speedup 1.0000x reference)
#include <cuda_runtime.h>

// Problem geometry: N = (262144, 65536, 16384), final block rank R = 21
#define NI 16384
#define A_ELEMS (21 * 21 * NI)
#define LOGDET_IDX (2 * A_ELEMS)
#define ZOUT_OFF (LOGDET_IDX + 1)   // odd float offset -> scalar stores only
#define ZOUT_PLANE (21 * NI)
#define TILE_I 64
#define NBLK (NI / TILE_I)          // 256
#define NTHREADS 448                // 14 warps

struct Cpx { float re, im; };

__device__ __forceinline__ Cpx cmul(Cpx a, Cpx b) {
    Cpx r; r.re = a.re * b.re - a.im * b.im; r.im = a.re * b.im + a.im * b.re; return r;
}
// a * conj(b)
__device__ __forceinline__ Cpx cmulc(Cpx a, Cpx b) {
    Cpx r; r.re = a.re * b.re + a.im * b.im; r.im = a.im * b.re - a.re * b.im; return r;
}
__device__ __forceinline__ Cpx cinv(Cpx a) {
    float d = 1.0f / (a.re * a.re + a.im * a.im);
    Cpx r; r.re = a.re * d; r.im = -a.im * d; return r;
}

// ---- packed f32x2 helpers ----
typedef unsigned long long u64;
__device__ __forceinline__ u64 pk2(float lo, float hi) {
    u64 r; asm("mov.b64 %0, {%1, %2};" : "=l"(r) : "f"(lo), "f"(hi)); return r;
}
__device__ __forceinline__ void upk2(u64 v, float& lo, float& hi) {
    asm("mov.b64 {%0, %1}, %2;" : "=f"(lo), "=f"(hi) : "l"(v));
}
#define MUL2(d, a, b)    asm("mul.rn.f32x2 %0, %1, %2;"     : "=l"(d) : "l"(a), "l"(b))
#define FMA2(d, a, b, c) asm("fma.rn.f32x2 %0, %1, %2, %3;" : "=l"(d) : "l"(a), "l"(b), "l"(c))
#define ADD2(d, a, b)    asm("add.rn.f32x2 %0, %1, %2;"     : "=l"(d) : "l"(a), "l"(b))

__device__ double g_ld[NBLK];
__device__ unsigned int g_count = 0;

__global__ void __launch_bounds__(NTHREADS, 2) kmain(
    const float* __restrict__ l00r, const float* __restrict__ l00i,
    const float* __restrict__ l01r, const float* __restrict__ l01i,
    const float* __restrict__ l02r, const float* __restrict__ l02i,
    const float* __restrict__ l11r, const float* __restrict__ l11i,
    const float* __restrict__ l12r, const float* __restrict__ l12i,
    const float* __restrict__ l22r, const float* __restrict__ l22i,
    const float* __restrict__ zre,  const float* __restrict__ zim,
    float* __restrict__ out)
{
    __shared__ float2 shT2[20 * 64];
    __shared__ float2 shZ[21 * 64];
    __shared__ float2 shL1[4 * 13 * 64];   // per s: P1[0..3], T1[4..7], a0[8..11], invS1[12]
    __shared__ float2 shM2[4 * 64];
    __shared__ float2 shInvS2[64];
    __shared__ float2 shW[64];
    __shared__ float2 shV[4 * 64];
    __shared__ float2 shU[4 * 64];
    __shared__ float  shLd[9];
    __shared__ int    shLast;

    const int lane = threadIdx.x & 31;
    const int warp = threadIdx.x >> 5;
    const int base = blockIdx.x * TILE_I;

    float facc = 0.f;
    float2 pre22r, pre22i;
    pre22r.x = pre22r.y = pre22i.x = pre22i.y = 0.f;
    Cpx rT1[4], rP1[4];

    if (warp < 8) {
        // ---- Phase 1: (s = warp&3, half = warp>>2), 1 i per thread ----
        const int s = warp & 3, half = warp >> 2;
        const int ii = half * 32 + lane;
        const int i = base + ii;
        const int m = s * NI + i;

        Cpx a0[4];
        Cpx M1; M1.re = 0.f; M1.im = 0.f;
        #pragma unroll
        for (int jj = 0; jj < 4; jj++) {
            const int idx = (jj * 4 + s) * NI + i;
            Cpx l00; l00.re = l00r[idx]; l00.im = l00i[idx];
            Cpx l01; l01.re = l01r[idx]; l01.im = l01i[idx];
            a0[jj] = cinv(l00);
            rT1[jj] = cmul(l01, a0[jj]);
            Cpx t = cmulc(rT1[jj], l01);
            M1.re += t.re; M1.im += t.im;
            facc += 0.5f * __logf(l00.re * l00.re + l00.im * l00.im);
        }
        Cpx S1; S1.re = l11r[m] - M1.re; S1.im = l11i[m] - M1.im;
        facc += 0.5f * __logf(S1.re * S1.re + S1.im * S1.im);
        const Cpx invS1 = cinv(S1);

        Cpx b[5];
        #pragma unroll
        for (int p = 0; p < 4; p++) {
            const int idx = (p * 4 + s) * NI + i;
            b[p].re = l02r[idx]; b[p].im = l02i[idx];
        }
        b[4].re = l12r[m]; b[4].im = l12i[m];

        Cpx w; w.re = 0.f; w.im = 0.f;
        #pragma unroll
        for (int p = 0; p < 4; p++) {
            Cpx t = cmulc(b[p], rT1[p]);
            w.re += t.re; w.im += t.im;
        }
        Cpx wm; wm.re = w.re - b[4].re; wm.im = w.im - b[4].im;

        Cpx t2b = cmul(invS1, b[4]);
        Cpx M2; M2.re = 0.f; M2.im = 0.f;
        #pragma unroll
        for (int q = 0; q < 4; q++) {
            rP1[q] = cmul(rT1[q], invS1);
            Cpx t2 = cmul(rP1[q], wm);
            Cpx t = cmul(a0[q], b[q]);
            t2.re += t.re; t2.im += t.im;
            shT2[(q * 4 + s) * 64 + ii] = make_float2(t2.re, t2.im);
            Cpx mm = cmulc(t2, b[q]);
            M2.re += mm.re; M2.im += mm.im;
            Cpx u = cmulc(b[q], rP1[q]);
            t2b.re -= u.re; t2b.im -= u.im;
        }
        shT2[(16 + s) * 64 + ii] = make_float2(t2b.re, t2b.im);
        Cpx mm = cmulc(t2b, b[4]);
        M2.re += mm.re; M2.im += mm.im;
        shM2[s * 64 + ii] = make_float2(M2.re, M2.im);

        #pragma unroll
        for (int q = 0; q < 4; q++) {
            shL1[(s * 13 + q) * 64 + ii]     = make_float2(rP1[q].re, rP1[q].im);
            shL1[(s * 13 + 4 + q) * 64 + ii] = make_float2(rT1[q].re, rT1[q].im);
            shL1[(s * 13 + 8 + q) * 64 + ii] = make_float2(a0[q].re, a0[q].im);
        }
        shL1[(s * 13 + 12) * 64 + ii] = make_float2(invS1.re, invS1.im);
    } else {
        // ---- z staging: warps 8..13 (ws=0..5): planes ws, ws+6, ws+12, (+18 if ws<3) ----
        const int ws = warp - 8;
        if (warp == 13) {
            pre22r = *(const float2*)(l22r + base + 2 * lane);
            pre22i = *(const float2*)(l22i + base + 2 * lane);
        }
        #pragma unroll
        for (int t = 0; t < 4; t++) {
            const int pl = ws + 6 * t;
            if (t < 3 || ws < 3) {
                float2 r = *(const float2*)(zre + pl * NI + base + 2 * lane);
                float2 im = *(const float2*)(zim + pl * NI + base + 2 * lane);
                *(float4*)&shZ[pl * 64 + 2 * lane] =
                    make_float4(r.x, im.x, r.y, im.y);
            }
        }
    }
    __syncthreads();

    // ---- Phase 1b ----
    if (warp < 8) {
        // V_s, U_s for this half
        const int s = warp & 3, half = warp >> 2;
        const int ii = half * 32 + lane;
        Cpx V; V.re = 0.f; V.im = 0.f;
        Cpx U; U.re = 0.f; U.im = 0.f;
        #pragma unroll
        for (int q = 0; q < 4; q++) {
            float2 zv = shZ[(q * 4 + s) * 64 + ii];
            Cpx z; z.re = zv.x; z.im = zv.y;
            Cpx tv = cmulc(z, rT1[q]);
            V.re += tv.re; V.im += tv.im;
            Cpx tu = cmulc(z, rP1[q]);
            U.re += tu.re; U.im += tu.im;
        }
        shV[s * 64 + ii] = make_float2(V.re, V.im);
        shU[s * 64 + ii] = make_float2(U.re, U.im);
    } else if (warp == 8) {
        // W (2 i per thread)
        Cpx W0, W1;
        W0.re = W0.im = W1.re = W1.im = 0.f;
        #pragma unroll
        for (int k = 0; k < 20; k++) {
            float4 tv = *(const float4*)&shT2[k * 64 + 2 * lane];
            float4 zv = *(const float4*)&shZ[k * 64 + 2 * lane];
            Cpx T0; T0.re = tv.x; T0.im = tv.y;
            Cpx T1c; T1c.re = tv.z; T1c.im = tv.w;
            Cpx z0; z0.re = zv.x; z0.im = zv.y;
            Cpx z1; z1.re = zv.z; z1.im = zv.w;
            Cpx t0 = cmulc(z0, T0); W0.re += t0.re; W0.im += t0.im;
            Cpx t1 = cmulc(z1, T1c); W1.re += t1.re; W1.im += t1.im;
        }
        float4 z20 = *(const float4*)&shZ[20 * 64 + 2 * lane];
        W0.re -= z20.x; W0.im -= z20.y;
        W1.re -= z20.z; W1.im -= z20.w;
        *(float4*)&shW[2 * lane] = make_float4(W0.re, W0.im, W1.re, W1.im);
    } else if (warp == 13) {
        // S2 / invS2 / log|S2| (2 i per thread)
        float4 m0 = *(const float4*)&shM2[0 * 64 + 2 * lane];
        float4 m1 = *(const float4*)&shM2[1 * 64 + 2 * lane];
        float4 m2 = *(const float4*)&shM2[2 * 64 + 2 * lane];
        float4 m3 = *(const float4*)&shM2[3 * 64 + 2 * lane];
        Cpx S0; S0.re = pre22r.x - (m0.x + m1.x + m2.x + m3.x);
                S0.im = pre22i.x - (m0.y + m1.y + m2.y + m3.y);
        Cpx S1c; S1c.re = pre22r.y - (m0.z + m1.z + m2.z + m3.z);
                 S1c.im = pre22i.y - (m0.w + m1.w + m2.w + m3.w);
        facc = 0.5f * __logf(S0.re * S0.re + S0.im * S0.im)
             + 0.5f * __logf(S1c.re * S1c.re + S1c.im * S1c.im);
        Cpx v0 = cinv(S0), v1 = cinv(S1c);
        *(float4*)&shInvS2[2 * lane] = make_float4(v0.re, v0.im, v1.re, v1.im);
    }
    if (warp < 8 || warp == 13) {
        #pragma unroll
        for (int off = 16; off > 0; off >>= 1)
            facc += __shfl_down_sync(0xffffffffu, facc, off);
        if (lane == 0) shLd[(warp < 8) ? warp : 8] = facc;
    }
    __syncthreads();

    // ---- Phase 2: warp w owns row w; warps 7..13 also own row w+7 ----
    const int i0 = base + 2 * lane;
    float4 ivv = *(const float4*)&shInvS2[2 * lane];
    Cpx iv0; iv0.re = ivv.x; iv0.im = ivv.y;
    Cpx iv1; iv1.re = ivv.z; iv1.im = ivv.w;

    const int nrows = (warp >= 7) ? 2 : 1;
    int  jA[2];  jA[0] = warp; jA[1] = warp + 7;
    u64 cA[2][2], cB[2][2];
    Cpx P1p[2][2], a0p[2][2], iS1[2][2];
    int sr[2], pr[2];
    bool isB2[2];
    float *oR[2], *oI[2];

    #pragma unroll
    for (int r = 0; r < 2; r++) {
        const int j = jA[r];
        sr[r] = j & 3; pr[r] = j >> 2; isB2[r] = (j == 20);
        oR[r] = out + (size_t)(j * 21) * NI + i0;
        oI[r] = out + A_ELEMS + (size_t)(j * 21) * NI + i0;
        #pragma unroll
        for (int u = 0; u < 2; u++) {
            P1p[r][u].re = P1p[r][u].im = 0.f;
            a0p[r][u].re = a0p[r][u].im = 0.f;
            iS1[r][u].re = iS1[r][u].im = 0.f;
        }
        if (r < nrows) {
            if (isB2[r]) {
                cA[r][0] = pk2(-iv0.re, iv0.im);
                cB[r][0] = pk2(iv0.im, iv0.re);
                cA[r][1] = pk2(-iv1.re, iv1.im);
                cB[r][1] = pk2(iv1.im, iv1.re);
            } else {
                float4 t = *(const float4*)&shT2[j * 64 + 2 * lane];
                Cpx T0; T0.re = t.x; T0.im = t.y;
                Cpx T1c; T1c.re = t.z; T1c.im = t.w;
                Cpx P0 = cmul(T0, iv0);
                Cpx P1c = cmul(T1c, iv1);
                cA[r][0] = pk2(P0.re, P0.im);
                cB[r][0] = pk2(P0.im, -P0.re);
                cA[r][1] = pk2(P1c.re, P1c.im);
                cB[r][1] = pk2(P1c.im, -P1c.re);
                if (pr[r] == 4) {
                    float4 v = *(const float4*)&shL1[(sr[r] * 13 + 12) * 64 + 2 * lane];
                    iS1[r][0].re = v.x; iS1[r][0].im = v.y;
                    iS1[r][1].re = v.z; iS1[r][1].im = v.w;
                } else {
                    float4 a = *(const float4*)&shL1[(sr[r] * 13 + pr[r]) * 64 + 2 * lane];
                    P1p[r][0].re = a.x; P1p[r][0].im = a.y;
                    P1p[r][1].re = a.z; P1p[r][1].im = a.w;
                    float4 c = *(const float4*)&shL1[(sr[r] * 13 + 8 + pr[r]) * 64 + 2 * lane];
                    a0p[r][0].re = c.x; a0p[r][0].im = c.y;
                    a0p[r][1].re = c.z; a0p[r][1].im = c.w;
                }
            }
        } else {
            cA[r][0] = cA[r][1] = cB[r][0] = cB[r][1] = pk2(0.f, 0.f);
        }
    }

    #pragma unroll
    for (int k = 0; k < 20; k++) {
        float4 tz = *(const float4*)&shT2[k * 64 + 2 * lane];
        u64 tkr0 = pk2(tz.x, tz.x), tki0 = pk2(tz.y, tz.y);
        u64 tkr1 = pk2(tz.z, tz.z), tki1 = pk2(tz.w, tz.w);
        #pragma unroll
        for (int r = 0; r < 2; r++) {
            if (r >= nrows) break;
            u64 v0, v1;
            MUL2(v0, cA[r][0], tkr0); FMA2(v0, cB[r][0], tki0, v0);
            MUL2(v1, cA[r][1], tkr1); FMA2(v1, cB[r][1], tki1, v1);
            if (!isB2[r] && (k & 3) == sr[r]) {
                const int q = k >> 2;
                float c0r, c0i, c1r, c1i;
                if (pr[r] == 4) {
                    if (q == 4) {
                        c0r = iS1[r][0].re; c0i = iS1[r][0].im;
                        c1r = iS1[r][1].re; c1i = iS1[r][1].im;
                    } else {
                        float4 p = *(const float4*)&shL1[(sr[r] * 13 + q) * 64 + 2 * lane];
                        c0r = -p.x; c0i = p.y;
                        c1r = -p.z; c1i = p.w;
                    }
                } else {
                    if (q == 4) {
                        c0r = -P1p[r][0].re; c0i = -P1p[r][0].im;
                        c1r = -P1p[r][1].re; c1i = -P1p[r][1].im;
                    } else {
                        float4 t1 = *(const float4*)&shL1[(sr[r] * 13 + 4 + q) * 64 + 2 * lane];
                        Cpx T1q0; T1q0.re = t1.x; T1q0.im = t1.y;
                        Cpx T1q1; T1q1.re = t1.z; T1q1.im = t1.w;
                        Cpx tt0 = cmulc(P1p[r][0], T1q0);
                        Cpx tt1 = cmulc(P1p[r][1], T1q1);
                        c0r = tt0.re; c0i = tt0.im;
                        c1r = tt1.re; c1i = tt1.im;
                        if (q == pr[r]) {
                            c0r += a0p[r][0].re; c0i += a0p[r][0].im;
                            c1r += a0p[r][1].re; c1i += a0p[r][1].im;
                        }
                    }
                }
                u64 cc0 = pk2(c0r, c0i), cc1 = pk2(c1r, c1i);
                ADD2(v0, v0, cc0); ADD2(v1, v1, cc1);
            }
            float v0r, v0i, v1r, v1i;
            upk2(v0, v0r, v0i); upk2(v1, v1r, v1i);
            *(float2*)(oR[r] + (size_t)k * NI) = make_float2(v0r, v1r);
            *(float2*)(oI[r] + (size_t)k * NI) = make_float2(v0i, v1i);
        }
    }

    // ---- k = 20 column + zout closed form ----
    float4 wv = *(const float4*)&shW[2 * lane];
    Cpx W0; W0.re = wv.x; W0.im = wv.y;
    Cpx W1; W1.re = wv.z; W1.im = wv.w;
    float4 z20v = *(const float4*)&shZ[20 * 64 + 2 * lane];

    #pragma unroll
    for (int r = 0; r < 2; r++) {
        if (r >= nrows) break;
        const int j = jA[r];
        Cpx v0, v1, zo0, zo1;
        if (isB2[r]) {
            v0 = iv0; v1 = iv1;
            Cpx z20a; z20a.re = z20v.x; z20a.im = z20v.y;
            Cpx z20b; z20b.re = z20v.z; z20b.im = z20v.w;
            Cpx Wp0; Wp0.re = W0.re + z20a.re; Wp0.im = W0.im + z20a.im;
            Cpx Wp1; Wp1.re = W1.re + z20b.re; Wp1.im = W1.im + z20b.im;
            Cpx cs0; cs0.re = -iv0.re; cs0.im = iv0.im;
            Cpx cs1; cs1.re = -iv1.re; cs1.im = iv1.im;
            Cpx t0 = cmul(cs0, Wp0), u0 = cmul(z20a, iv0);
            Cpx t1 = cmul(cs1, Wp1), u1 = cmul(z20b, iv1);
            zo0.re = t0.re + u0.re; zo0.im = t0.im + u0.im;
            zo1.re = t1.re + u1.re; zo1.im = t1.im + u1.im;
        } else {
            float p0r, p0i, p1r, p1i;
            upk2(cA[r][0], p0r, p0i); upk2(cA[r][1], p1r, p1i);
            Cpx P0; P0.re = p0r; P0.im = p0i;
            Cpx P1c; P1c.re = p1r; P1c.im = p1i;
            v0.re = -P0.re; v0.im = -P0.im;
            v1.re = -P1c.re; v1.im = -P1c.im;
            zo0 = cmul(P0, W0); zo1 = cmul(P1c, W1);
            float4 z16v = *(const float4*)&shZ[(16 + sr[r]) * 64 + 2 * lane];
            Cpx z16a; z16a.re = z16v.x; z16a.im = z16v.y;
            Cpx z16b; z16b.re = z16v.z; z16b.im = z16v.w;
            if (pr[r] == 4) {
                float4 uv = *(const float4*)&shU[sr[r] * 64 + 2 * lane];
                Cpx t0 = cmul(z16a, iS1[r][0]);
                Cpx t1 = cmul(z16b, iS1[r][1]);
                zo0.re += t0.re - uv.x; zo0.im += t0.im - uv.y;
                zo1.re += t1.re - uv.z; zo1.im += t1.im - uv.w;
            } else {
                float4 vv = *(const float4*)&shV[sr[r] * 64 + 2 * lane];
                Cpx vm0; vm0.re = vv.x - z16a.re; vm0.im = vv.y - z16a.im;
                Cpx vm1; vm1.re = vv.z - z16b.re; vm1.im = vv.w - z16b.im;
                Cpx t0 = cmul(P1p[r][0], vm0);
                Cpx t1 = cmul(P1p[r][1], vm1);
                float4 zpv = *(const float4*)&shZ[(pr[r] * 4 + sr[r]) * 64 + 2 * lane];
                Cpx zpa; zpa.re = zpv.x; zpa.im = zpv.y;
                Cpx zpb; zpb.re = zpv.z; zpb.im = zpv.w;
                Cpx u0 = cmul(zpa, a0p[r][0]);
                Cpx u1 = cmul(zpb, a0p[r][1]);
                zo0.re += t0.re + u0.re; zo0.im += t0.im + u0.im;
                zo1.re += t1.re + u1.re; zo1.im += t1.im + u1.im;
            }
        }
        *(float2*)(oR[r] + (size_t)20 * NI) = make_float2(v0.re, v1.re);
        *(float2*)(oI[r] + (size_t)20 * NI) = make_float2(v0.im, v1.im);
        float* zoR = out + ZOUT_OFF + (size_t)j * NI + i0;
        float* zoI = out + ZOUT_OFF + ZOUT_PLANE + (size_t)j * NI + i0;
        zoR[0] = zo0.re; zoR[1] = zo1.re;
        zoI[0] = zo0.im; zoI[1] = zo1.im;
    }

    // ---- logdet: per-block partial, last block finalizes ----
    if (threadIdx.x == 0) {
        double p = 0.0;
        #pragma unroll
        for (int w = 0; w < 9; w++) p += (double)shLd[w];
        g_ld[blockIdx.x] = p;
        __threadfence();
        unsigned int v = atomicAdd(&g_count, 1u);
        shLast = (v == NBLK - 1) ? 1 : 0;
    }
    __syncthreads();
    if (shLast && warp == 0) {
        __threadfence();
        double a = 0.0;
        #pragma unroll
        for (int q = 0; q < NBLK / 32; q++)
            a += g_ld[q * 32 + lane];
        #pragma unroll
        for (int off = 16; off > 0; off >>= 1)
            a += __shfl_xor_sync(0xffffffffu, a, off);
        if (lane == 0) {
            out[LOGDET_IDX] = (float)a;
            g_count = 0;   // reset for graph replay
        }
    }
}

extern "C" void kernel_launch(void* const* d_in, const int* in_sizes, int n_in,
                              void* d_out, int out_size)
{
    const float* l00r = (const float*)d_in[0];
    const float* l00i = (const float*)d_in[1];
    const float* l01r = (const float*)d_in[2];
    const float* l01i = (const float*)d_in[3];
    const float* l02r = (const float*)d_in[4];
    const float* l02i = (const float*)d_in[5];
    const float* l11r = (const float*)d_in[6];
    const float* l11i = (const float*)d_in[7];
    const float* l12r = (const float*)d_in[8];
    const float* l12i = (const float*)d_in[9];
    const float* l22r = (const float*)d_in[10];
    const float* l22i = (const float*)d_in[11];
    const float* zre  = (const float*)d_in[12];
    const float* zim  = (const float*)d_in[13];
    float* out = (float*)d_out;

    kmain<<<NBLK, NTHREADS>>>(l00r, l00i, l01r, l01i, l02r, l02i,
                              l11r, l11i, l12r, l12i, l22r, l22i,
                              zre, zim, out);
}

// round 17
// speedup vs baseline: 1.0946x; 1.0946x over previous
#include <cuda_runtime.h>

// Problem geometry: N = (262144, 65536, 16384), final block rank R = 21
#define NI 16384
#define A_ELEMS (21 * 21 * NI)
#define LOGDET_IDX (2 * A_ELEMS)
#define ZOUT_OFF (LOGDET_IDX + 1)   // odd float offset -> scalar stores only
#define ZOUT_PLANE (21 * NI)
#define TILE_I 32
#define NBLK (NI / TILE_I)          // 512
#define NTHREADS 224                // 7 warps, 3 rows each

struct Cpx { float re, im; };

__device__ __forceinline__ Cpx cmul(Cpx a, Cpx b) {
    Cpx r; r.re = a.re * b.re - a.im * b.im; r.im = a.re * b.im + a.im * b.re; return r;
}
// a * conj(b)
__device__ __forceinline__ Cpx cmulc(Cpx a, Cpx b) {
    Cpx r; r.re = a.re * b.re + a.im * b.im; r.im = a.im * b.re - a.re * b.im; return r;
}
__device__ __forceinline__ Cpx cinv(Cpx a) {
    float d = 1.0f / (a.re * a.re + a.im * a.im);
    Cpx r; r.re = a.re * d; r.im = -a.im * d; return r;
}

__device__ double g_ld[NBLK];
__device__ unsigned int g_count = 0;

__global__ void __launch_bounds__(NTHREADS, 6) kmain(
    const float* __restrict__ l00r, const float* __restrict__ l00i,
    const float* __restrict__ l01r, const float* __restrict__ l01i,
    const float* __restrict__ l02r, const float* __restrict__ l02i,
    const float* __restrict__ l11r, const float* __restrict__ l11i,
    const float* __restrict__ l12r, const float* __restrict__ l12i,
    const float* __restrict__ l22r, const float* __restrict__ l22i,
    const float* __restrict__ zre,  const float* __restrict__ zim,
    float* __restrict__ out)
{
    __shared__ float2 shT2[20 * 32];
    __shared__ float2 shZ[21 * 32];
    __shared__ float2 shL1[4 * 13 * 32];   // per s: P1[0..3], T1[4..7], a0[8..11], invS1[12]
    __shared__ float2 shM2[4 * 32];
    __shared__ float2 shInvS2[32];
    __shared__ float2 shW[32];
    __shared__ float2 shV[4 * 32];
    __shared__ float2 shU[4 * 32];
    __shared__ float  shLd[5];
    __shared__ int    shLast;

    const int lane = threadIdx.x & 31;
    const int warp = threadIdx.x >> 5;
    const int i = blockIdx.x * TILE_I + lane;

    float facc = 0.f;
    float pre22r = 0.f, pre22i = 0.f;
    Cpx rT1[4], rP1[4];

    if (warp < 4) {
        // ---- Phase 1: s = warp ----
        const int s = warp;
        const int m = s * NI + i;

        Cpx a0[4];
        Cpx M1; M1.re = 0.f; M1.im = 0.f;
        #pragma unroll
        for (int jj = 0; jj < 4; jj++) {
            const int idx = (jj * 4 + s) * NI + i;
            Cpx l00; l00.re = l00r[idx]; l00.im = l00i[idx];
            Cpx l01; l01.re = l01r[idx]; l01.im = l01i[idx];
            a0[jj] = cinv(l00);
            rT1[jj] = cmul(l01, a0[jj]);
            Cpx t = cmulc(rT1[jj], l01);
            M1.re += t.re; M1.im += t.im;
            facc += 0.5f * __logf(l00.re * l00.re + l00.im * l00.im);
        }
        Cpx S1; S1.re = l11r[m] - M1.re; S1.im = l11i[m] - M1.im;
        facc += 0.5f * __logf(S1.re * S1.re + S1.im * S1.im);
        const Cpx invS1 = cinv(S1);

        Cpx b[5];
        #pragma unroll
        for (int p = 0; p < 4; p++) {
            const int idx = (p * 4 + s) * NI + i;
            b[p].re = l02r[idx]; b[p].im = l02i[idx];
        }
        b[4].re = l12r[m]; b[4].im = l12i[m];

        Cpx w; w.re = 0.f; w.im = 0.f;
        #pragma unroll
        for (int p = 0; p < 4; p++) {
            Cpx t = cmulc(b[p], rT1[p]);
            w.re += t.re; w.im += t.im;
        }
        Cpx wm; wm.re = w.re - b[4].re; wm.im = w.im - b[4].im;

        Cpx t2b = cmul(invS1, b[4]);
        Cpx M2; M2.re = 0.f; M2.im = 0.f;
        #pragma unroll
        for (int q = 0; q < 4; q++) {
            rP1[q] = cmul(rT1[q], invS1);
            Cpx t2 = cmul(rP1[q], wm);
            Cpx t = cmul(a0[q], b[q]);
            t2.re += t.re; t2.im += t.im;
            shT2[(q * 4 + s) * 32 + lane] = make_float2(t2.re, t2.im);
            Cpx mm = cmulc(t2, b[q]);
            M2.re += mm.re; M2.im += mm.im;
            Cpx u = cmulc(b[q], rP1[q]);
            t2b.re -= u.re; t2b.im -= u.im;
        }
        shT2[(16 + s) * 32 + lane] = make_float2(t2b.re, t2b.im);
        Cpx mm = cmulc(t2b, b[4]);
        M2.re += mm.re; M2.im += mm.im;
        shM2[s * 32 + lane] = make_float2(M2.re, M2.im);

        #pragma unroll
        for (int q = 0; q < 4; q++) {
            shL1[(s * 13 + q) * 32 + lane]     = make_float2(rP1[q].re, rP1[q].im);
            shL1[(s * 13 + 4 + q) * 32 + lane] = make_float2(rT1[q].re, rT1[q].im);
            shL1[(s * 13 + 8 + q) * 32 + lane] = make_float2(a0[q].re, a0[q].im);
        }
        shL1[(s * 13 + 12) * 32 + lane] = make_float2(invS1.re, invS1.im);
    } else {
        // ---- z staging: warps 4..6 load 7 planes each ----
        if (warp == 4) { pre22r = l22r[i]; pre22i = l22i[i]; }
        const int pbase = (warp - 4) * 7;
        #pragma unroll
        for (int t = 0; t < 7; t++) {
            const int pl = pbase + t;
            shZ[pl * 32 + lane] = make_float2(zre[pl * NI + i], zim[pl * NI + i]);
        }
    }
    __syncthreads();

    // ---- Phase 1b ----
    if (warp < 4) {
        const int s = warp;
        Cpx V; V.re = 0.f; V.im = 0.f;
        Cpx U; U.re = 0.f; U.im = 0.f;
        #pragma unroll
        for (int q = 0; q < 4; q++) {
            float2 zv = shZ[(q * 4 + s) * 32 + lane];
            Cpx z; z.re = zv.x; z.im = zv.y;
            Cpx tv = cmulc(z, rT1[q]);
            V.re += tv.re; V.im += tv.im;
            Cpx tu = cmulc(z, rP1[q]);
            U.re += tu.re; U.im += tu.im;
        }
        shV[s * 32 + lane] = make_float2(V.re, V.im);
        shU[s * 32 + lane] = make_float2(U.re, U.im);
    } else if (warp == 4) {
        float2 m0 = shM2[0 * 32 + lane], m1 = shM2[1 * 32 + lane],
               m2 = shM2[2 * 32 + lane], m3 = shM2[3 * 32 + lane];
        Cpx S2; S2.re = pre22r - (m0.x + m1.x + m2.x + m3.x);
                S2.im = pre22i - (m0.y + m1.y + m2.y + m3.y);
        facc = 0.5f * __logf(S2.re * S2.re + S2.im * S2.im);
        Cpx inv = cinv(S2);
        shInvS2[lane] = make_float2(inv.re, inv.im);
    } else if (warp == 5) {
        Cpx W; W.re = 0.f; W.im = 0.f;
        #pragma unroll
        for (int k = 0; k < 20; k++) {
            float2 tv = shT2[k * 32 + lane];
            float2 zv = shZ[k * 32 + lane];
            Cpx T; T.re = tv.x; T.im = tv.y;
            Cpx z; z.re = zv.x; z.im = zv.y;
            Cpx t = cmulc(z, T);
            W.re += t.re; W.im += t.im;
        }
        float2 z20 = shZ[20 * 32 + lane];
        W.re -= z20.x; W.im -= z20.y;
        shW[lane] = make_float2(W.re, W.im);
    }
    if (warp < 5) {
        #pragma unroll
        for (int off = 16; off > 0; off >>= 1)
            facc += __shfl_down_sync(0xffffffffu, facc, off);
        if (lane == 0) shLd[warp] = facc;
    }
    __syncthreads();

    // ---- Phase 2: warp w owns rows w, w+7, w+14 ----
    float2 iv = shInvS2[lane];
    Cpx invS2; invS2.re = iv.x; invS2.im = iv.y;

    Cpx P2[3], P1p[3], a0p[3], iS1[3];
    int sr[3], pr[3];
    bool isB2[3];
    int oOff[3];                 // int32 offsets: out[oOff + k*NI] (re), +A_ELEMS (im)

    #pragma unroll
    for (int r = 0; r < 3; r++) {
        const int j = warp + 7 * r;
        sr[r] = j & 3; pr[r] = j >> 2; isB2[r] = (j == 20);
        oOff[r] = j * 21 * NI + i;
        P2[r].re = P2[r].im = 0.f;
        P1p[r].re = P1p[r].im = 0.f;
        a0p[r].re = a0p[r].im = 0.f;
        iS1[r].re = iS1[r].im = 0.f;
        if (!isB2[r]) {
            float2 t = shT2[j * 32 + lane];
            Cpx T2j; T2j.re = t.x; T2j.im = t.y;
            P2[r] = cmul(T2j, invS2);
            if (pr[r] == 4) {
                float2 v = shL1[(sr[r] * 13 + 12) * 32 + lane];
                iS1[r].re = v.x; iS1[r].im = v.y;
            } else {
                float2 a = shL1[(sr[r] * 13 + pr[r]) * 32 + lane];
                P1p[r].re = a.x; P1p[r].im = a.y;
                float2 c = shL1[(sr[r] * 13 + 8 + pr[r]) * 32 + lane];
                a0p[r].re = c.x; a0p[r].im = c.y;
            }
        }
    }

    // ---- zout (closed form) stored up-front, frees registers for k-loop ----
    {
        float2 wv = shW[lane];
        Cpx W; W.re = wv.x; W.im = wv.y;
        #pragma unroll
        for (int r = 0; r < 3; r++) {
            const int j = warp + 7 * r;
            Cpx zo;
            if (isB2[r]) {
                float2 z20v = shZ[20 * 32 + lane];
                Cpx z20; z20.re = z20v.x; z20.im = z20v.y;
                Cpx Wp; Wp.re = W.re + z20.re; Wp.im = W.im + z20.im;
                Cpx cs; cs.re = -invS2.re; cs.im = invS2.im;   // -conj(invS2)
                Cpx t = cmul(cs, Wp);
                Cpx u = cmul(z20, invS2);
                zo.re = t.re + u.re; zo.im = t.im + u.im;
            } else {
                zo = cmul(P2[r], W);
                float2 z16v = shZ[(16 + sr[r]) * 32 + lane];
                Cpx z16; z16.re = z16v.x; z16.im = z16v.y;
                if (pr[r] == 4) {
                    float2 uv = shU[sr[r] * 32 + lane];
                    Cpx t1 = cmul(z16, iS1[r]);
                    zo.re += t1.re - uv.x; zo.im += t1.im - uv.y;
                } else {
                    float2 vv = shV[sr[r] * 32 + lane];
                    Cpx vm; vm.re = vv.x - z16.re; vm.im = vv.y - z16.im;
                    Cpx t1 = cmul(P1p[r], vm);
                    float2 zpv = shZ[(pr[r] * 4 + sr[r]) * 32 + lane];
                    Cpx zp; zp.re = zpv.x; zp.im = zpv.y;
                    Cpx t2 = cmul(zp, a0p[r]);
                    zo.re += t1.re + t2.re; zo.im += t1.im + t2.im;
                }
            }
            out[ZOUT_OFF + j * NI + i] = zo.re;
            out[ZOUT_OFF + ZOUT_PLANE + j * NI + i] = zo.im;
        }
    }

    // ---- main k-loop: A rows ----
    #pragma unroll
    for (int k = 0; k < 20; k++) {
        float2 tv = shT2[k * 32 + lane];
        Cpx Tk; Tk.re = tv.x; Tk.im = tv.y;
        #pragma unroll
        for (int r = 0; r < 3; r++) {
            Cpx v;
            if (isB2[r]) {
                Cpx P = cmul(Tk, invS2);
                v.re = -P.re; v.im = P.im;                 // -conj(P2[k])
            } else {
                v = cmulc(P2[r], Tk);
                if ((k & 3) == sr[r]) {                    // warp-uniform hit
                    const int q = k >> 2;
                    if (pr[r] == 4) {
                        if (q == 4) { v.re += iS1[r].re; v.im += iS1[r].im; }
                        else {
                            float2 p1q = shL1[(sr[r] * 13 + q) * 32 + lane];
                            v.re -= p1q.x; v.im += p1q.y;  // -conj(P1[q])
                        }
                    } else {
                        if (q == 4) { v.re -= P1p[r].re; v.im -= P1p[r].im; }
                        else {
                            float2 t1 = shL1[(sr[r] * 13 + 4 + q) * 32 + lane];
                            Cpx T1q; T1q.re = t1.x; T1q.im = t1.y;
                            Cpx tt = cmulc(P1p[r], T1q);
                            v.re += tt.re; v.im += tt.im;
                            if (q == pr[r]) { v.re += a0p[r].re; v.im += a0p[r].im; }
                        }
                    }
                }
            }
            out[oOff[r] + k * NI] = v.re;
            out[A_ELEMS + oOff[r] + k * NI] = v.im;
        }
    }
    // column k = 20
    #pragma unroll
    for (int r = 0; r < 3; r++) {
        Cpx v;
        if (isB2[r]) v = invS2;
        else { v.re = -P2[r].re; v.im = -P2[r].im; }
        out[oOff[r] + 20 * NI] = v.re;
        out[A_ELEMS + oOff[r] + 20 * NI] = v.im;
    }

    // ---- logdet: per-block partial, last block finalizes ----
    if (threadIdx.x == 0) {
        double p = (double)(shLd[0] + shLd[1] + shLd[2] + shLd[3] + shLd[4]);
        g_ld[blockIdx.x] = p;
        __threadfence();
        unsigned int v = atomicAdd(&g_count, 1u);
        shLast = (v == NBLK - 1) ? 1 : 0;
    }
    __syncthreads();
    if (shLast && warp == 0) {
        __threadfence();
        double a = 0.0;
        #pragma unroll
        for (int q = 0; q < NBLK / 32; q++)
            a += g_ld[q * 32 + lane];
        #pragma unroll
        for (int off = 16; off > 0; off >>= 1)
            a += __shfl_xor_sync(0xffffffffu, a, off);
        if (lane == 0) {
            out[LOGDET_IDX] = (float)a;
            g_count = 0;   // reset for graph replay
        }
    }
}

extern "C" void kernel_launch(void* const* d_in, const int* in_sizes, int n_in,
                              void* d_out, int out_size)
{
    const float* l00r = (const float*)d_in[0];
    const float* l00i = (const float*)d_in[1];
    const float* l01r = (const float*)d_in[2];
    const float* l01i = (const float*)d_in[3];
    const float* l02r = (const float*)d_in[4];
    const float* l02i = (const float*)d_in[5];
    const float* l11r = (const float*)d_in[6];
    const float* l11i = (const float*)d_in[7];
    const float* l12r = (const float*)d_in[8];
    const float* l12i = (const float*)d_in[9];
    const float* l22r = (const float*)d_in[10];
    const float* l22i = (const float*)d_in[11];
    const float* zre  = (const float*)d_in[12];
    const float* zim  = (const float*)d_in[13];
    float* out = (float*)d_out;

    kmain<<<NBLK, NTHREADS>>>(l00r, l00i, l01r, l01i, l02r, l02i,
                              l11r, l11i, l12r, l12i, l22r, l22i,
                              zre, zim, out);
}